// round 14
// baseline (speedup 1.0000x reference)
#include <cuda_runtime.h>
#include <cstdint>
#include <cstddef>
#include <math.h>

// Problem dims
#define BATCH 64
#define EDIM 2048
#define HDIM 1024
#define SLEN 512
#define VOCAB 32000

#define SPLIT_1  8    // split-K for fused first launch (t1|g1|t2)
#define SPLIT_G2 8    // split-K for g2 (m@Wm)
#define SPLIT_O  2    // split-K for logits gemm
#define ATT_SPLIT 16  // split-S for attention

// ---------------- scratch (device globals; no allocation allowed) ----------------
__device__ float d_m   [BATCH * HDIM];
__device__ float d_hc  [BATCH * 2 * HDIM];
__device__ float d_P1  [SPLIT_1  * BATCH * HDIM];       // partials x@Wmx
__device__ float d_P2  [SPLIT_1  * BATCH * HDIM];       // partials h0@Wmh
__device__ float d_P3  [SPLIT_1  * BATCH * 4 * HDIM];   // partials x@Wx
__device__ float d_P4  [SPLIT_G2 * BATCH * 4 * HDIM];   // partials m@Wm
__device__ float d_PO  [SPLIT_O  * BATCH * VOCAB];      // partials logits
__device__ float d_pctx[BATCH * ATT_SPLIT * HDIM];
__device__ float d_pms [BATCH * ATT_SPLIT * 2];

// ---------------- helpers ----------------
// pack two fp32 into bf16x2 hi parts + bf16x2 lo residuals (memory order: lo half = x)
__device__ __forceinline__ void split2(float x, float y, unsigned& hi, unsigned& lo) {
    asm("cvt.rn.bf16x2.f32 %0, %1, %2;" : "=r"(hi) : "f"(y), "f"(x));
    float hx = __uint_as_float(hi << 16);
    float hy = __uint_as_float(hi & 0xffff0000u);
    asm("cvt.rn.bf16x2.f32 %0, %1, %2;" : "=r"(lo) : "f"(y - hy), "f"(x - hx));
}

__device__ __forceinline__ void ldm_x4(unsigned* r, unsigned saddr) {
    asm volatile("ldmatrix.sync.aligned.m8n8.x4.shared.b16 {%0,%1,%2,%3}, [%4];"
                 : "=r"(r[0]), "=r"(r[1]), "=r"(r[2]), "=r"(r[3]) : "r"(saddr));
}
__device__ __forceinline__ void ldm_x4t(unsigned* r, unsigned saddr) {
    asm volatile("ldmatrix.sync.aligned.m8n8.x4.trans.shared.b16 {%0,%1,%2,%3}, [%4];"
                 : "=r"(r[0]), "=r"(r[1]), "=r"(r[2]), "=r"(r[3]) : "r"(saddr));
}

#define MMA_BF16(d, a, b0, b1) \
    asm volatile("mma.sync.aligned.m16n8k16.row.col.f32.bf16.bf16.f32 " \
        "{%0,%1,%2,%3}, {%4,%5,%6,%7}, {%8,%9}, {%0,%1,%2,%3};" \
        : "+f"(d[0]), "+f"(d[1]), "+f"(d[2]), "+f"(d[3]) \
        : "r"(a[0]), "r"(a[1]), "r"(a[2]), "r"(a[3]), "r"(b0), "r"(b1))

// Smem strides in halfs (A rows 80B -> 5r mod 8 distinct; B rows 272B -> 17k mod 8 distinct)
#define A_ST 40
#define B_ST 136
#define A_BUF (64 * A_ST)   // 2560 halfs per buffer
#define B_BUF (32 * B_ST)   // 4352 halfs per buffer
#define GEMM_SMEM_BYTES ((2 * A_BUF * 2 + 2 * B_BUF * 2) * 2)  // 55296 B

// GEMM section: C[64][N] (+split-K partials) = A[64][K] @ W[K][N]
struct GemmSec {
    const float* A;
    const float* W;
    float*       C;
    int          K;
    int          N;
};

// ---------------- bf16 3-term GEMM (proven core, 3-section dispatch) ----------------
__global__ __launch_bounds__(256) void bf16gemm(
    GemmSec s0, GemmSec s1, GemmSec s2, int nb0, int nb1)
{
    extern __shared__ unsigned short sh[];
    unsigned short* Ahi = sh;                    // [2][A_BUF]
    unsigned short* Alo = sh + 2 * A_BUF;        // [2][A_BUF]
    unsigned short* Bhi = sh + 4 * A_BUF;        // [2][B_BUF]
    unsigned short* Blo = Bhi + 2 * B_BUF;       // [2][B_BUF]

    const int tid  = threadIdx.x;
    const int lane = tid & 31;
    const int warp = tid >> 5;
    const int wm   = warp & 1;
    const int wn   = warp >> 1;
    const int qr   = lane >> 2;
    const int qc   = lane & 3;

    // 3-section dispatch
    GemmSec s;
    int nbx = blockIdx.x;
    if (nbx < nb0)             { s = s0; }
    else if (nbx < nb0 + nb1)  { s = s1; nbx -= nb0; }
    else                       { s = s2; nbx -= nb0 + nb1; }
    const float* A = s.A;
    const float* W = s.W;
    const int K = s.K;
    const int N = s.N;
    const int n0 = nbx * 128;

    const int Sy   = gridDim.y;
    const int Kc   = K / Sy;
    const int kbeg = blockIdx.y * Kc;
    const int nk   = Kc / 32;
    float* Cb = (Sy > 1) ? (s.C + (size_t)blockIdx.y * 64 * N) : s.C;

    const int aR = tid >> 2;
    const int aC = (tid & 3) * 8;
    const int bR = tid >> 3;
    const int bC = (tid & 7) * 16;

    float4 ar0, ar1, br0, br1, br2, br3;
    {
        const float* ag = A + (size_t)aR * K + kbeg + aC;
        ar0 = *(const float4*)ag;
        ar1 = *(const float4*)(ag + 4);
        const float* bg = W + (size_t)(kbeg + bR) * N + n0 + bC;
        br0 = *(const float4*)bg;
        br1 = *(const float4*)(bg + 4);
        br2 = *(const float4*)(bg + 8);
        br3 = *(const float4*)(bg + 12);
    }

    float d[2][4][4];
#pragma unroll
    for (int i = 0; i < 2; i++)
#pragma unroll
        for (int j = 0; j < 4; j++)
#pragma unroll
            for (int q = 0; q < 4; q++) d[i][j][q] = 0.f;

    const unsigned sAh = (unsigned)__cvta_generic_to_shared(Ahi);
    const unsigned sAl = (unsigned)__cvta_generic_to_shared(Alo);
    const unsigned sBh = (unsigned)__cvta_generic_to_shared(Bhi);
    const unsigned sBl = (unsigned)__cvta_generic_to_shared(Blo);

    for (int t = 0; t < nk; t++) {
        const int buf = t & 1;
        // ---- convert tile t -> buffer buf ----
        {
            unsigned short* AhiB = Ahi + buf * A_BUF;
            unsigned short* AloB = Alo + buf * A_BUF;
            unsigned short* BhiB = Bhi + buf * B_BUF;
            unsigned short* BloB = Blo + buf * B_BUF;

            uint4 h, l;
            split2(ar0.x, ar0.y, h.x, l.x);
            split2(ar0.z, ar0.w, h.y, l.y);
            split2(ar1.x, ar1.y, h.z, l.z);
            split2(ar1.z, ar1.w, h.w, l.w);
            *(uint4*)&AhiB[aR * A_ST + aC] = h;
            *(uint4*)&AloB[aR * A_ST + aC] = l;

            split2(br0.x, br0.y, h.x, l.x);
            split2(br0.z, br0.w, h.y, l.y);
            split2(br1.x, br1.y, h.z, l.z);
            split2(br1.z, br1.w, h.w, l.w);
            *(uint4*)&BhiB[bR * B_ST + bC] = h;
            *(uint4*)&BloB[bR * B_ST + bC] = l;

            split2(br2.x, br2.y, h.x, l.x);
            split2(br2.z, br2.w, h.y, l.y);
            split2(br3.x, br3.y, h.z, l.z);
            split2(br3.z, br3.w, h.w, l.w);
            *(uint4*)&BhiB[bR * B_ST + bC + 8] = h;
            *(uint4*)&BloB[bR * B_ST + bC + 8] = l;
        }
        // ---- prefetch tile t+1 into registers ----
        if (t + 1 < nk) {
            const int k0 = kbeg + (t + 1) * 32;
            const float* ag = A + (size_t)aR * K + k0 + aC;
            ar0 = *(const float4*)ag;
            ar1 = *(const float4*)(ag + 4);
            const float* bg = W + (size_t)(k0 + bR) * N + n0 + bC;
            br0 = *(const float4*)bg;
            br1 = *(const float4*)(bg + 4);
            br2 = *(const float4*)(bg + 8);
            br3 = *(const float4*)(bg + 12);
        }
        __syncthreads();  // convert(t) visible; implies MMA(t-1) fully drained

        // ---- MMA from buffer buf: 2 k-chunks of 16 ----
#pragma unroll
        for (int kc = 0; kc < 2; kc++) {
            const unsigned aoff = (unsigned)((buf * A_BUF +
                (wm * 32 + (lane & 15)) * A_ST + kc * 16 + (lane >> 4) * 8) * 2);
            unsigned ah[2][4], al[2][4];
            ldm_x4(ah[0], sAh + aoff);
            ldm_x4(ah[1], sAh + aoff + 16 * A_ST * 2);
            ldm_x4(al[0], sAl + aoff);
            ldm_x4(al[1], sAl + aoff + 16 * A_ST * 2);

            const unsigned boff = (unsigned)((buf * B_BUF +
                (kc * 16 + (lane & 15)) * B_ST + wn * 32 + (lane >> 4) * 8) * 2);
            unsigned bh[2][4], bl[2][4];
            ldm_x4t(bh[0], sBh + boff);
            ldm_x4t(bh[1], sBh + boff + 16 * 2);
            ldm_x4t(bl[0], sBl + boff);
            ldm_x4t(bl[1], sBl + boff + 16 * 2);

#pragma unroll
            for (int mi = 0; mi < 2; mi++)
#pragma unroll
                for (int ni = 0; ni < 4; ni++) {
                    const int p = ni >> 1, q = (ni & 1) * 2;
                    MMA_BF16(d[mi][ni], ah[mi], bh[p][q], bh[p][q + 1]);
                    MMA_BF16(d[mi][ni], al[mi], bh[p][q], bh[p][q + 1]);
                    MMA_BF16(d[mi][ni], ah[mi], bl[p][q], bl[p][q + 1]);
                }
        }
    }

#pragma unroll
    for (int mi = 0; mi < 2; mi++) {
        const int r = wm * 32 + mi * 16 + qr;
#pragma unroll
        for (int ni = 0; ni < 4; ni++) {
            const int c = n0 + wn * 32 + ni * 8 + qc * 2;
            float2 v0 = make_float2(d[mi][ni][0], d[mi][ni][1]);
            float2 v1 = make_float2(d[mi][ni][2], d[mi][ni][3]);
            *(float2*)(Cb + (size_t)r * N + c)       = v0;
            *(float2*)(Cb + (size_t)(r + 8) * N + c) = v1;
        }
    }
}

// ---------------- m = (x@Wmx + bmx) * (h0@Wmh + bmh) ----------------
__global__ void m_kernel(const float* __restrict__ P1, const float* __restrict__ P2,
                         const float* __restrict__ bmx, const float* __restrict__ bmh,
                         float* __restrict__ m) {
    int idx = blockIdx.x * 256 + threadIdx.x;
    int j = idx & (HDIM - 1);
    float a = bmx[j], c = bmh[j];
#pragma unroll
    for (int s = 0; s < SPLIT_1; s++) {
        a += P1[(size_t)s * (BATCH * HDIM) + idx];
        c += P2[(size_t)s * (BATCH * HDIM) + idx];
    }
    m[idx] = a * c;
}

// ---------------- gates: reduce partials, LSTM cell -> h into hc[:, :H] ----------------
__global__ void gates_kernel(const float* __restrict__ P3, const float* __restrict__ P4,
                             const float* __restrict__ bx, const float* __restrict__ bm,
                             const float* __restrict__ c0, float* __restrict__ hc) {
    int idx = blockIdx.x * 256 + threadIdx.x;
    int b = idx >> 10, j = idx & (HDIM - 1);
    float gv[4];
#pragma unroll
    for (int q = 0; q < 4; q++) {
        int colq = j + q * HDIM;
        float g = bx[colq] + bm[colq];
        size_t off = (size_t)b * (4 * HDIM) + colq;
#pragma unroll
        for (int s = 0; s < SPLIT_1; s++)
            g += P3[(size_t)s * (BATCH * 4 * HDIM) + off];
#pragma unroll
        for (int s = 0; s < SPLIT_G2; s++)
            g += P4[(size_t)s * (BATCH * 4 * HDIM) + off];
        gv[q] = g;
    }
    float f  = 1.f / (1.f + expf(-gv[0]));
    float ii = 1.f / (1.f + expf(-gv[1]));
    float o  = 1.f / (1.f + expf(-gv[2]));
    float ct = tanhf(gv[3]);
    float c  = f * c0[idx] + ii * ct;
    hc[(size_t)b * (2 * HDIM) + j] = o * tanhf(c);
}

// ---------------- attention partial v2: warp-local register flash ----------------
// grid (B, ATT_SPLIT), 256 threads (8 warps). Each warp owns 4 sv rows; rows stay
// in registers for both the dot and the ctx update. No smem / barriers in hot loop.
__global__ __launch_bounds__(256) void attn_partial(
    const float* __restrict__ hc, const float* __restrict__ sv,
    float* __restrict__ pctx, float* __restrict__ pms)
{
    __shared__ float hs[HDIM];
    __shared__ float wctx[8][HDIM];
    __shared__ float wms[8][2];

    const int b   = blockIdx.x;
    const int sp  = blockIdx.y;
    const int tid = threadIdx.x;
    const int warp = tid >> 5, lane = tid & 31;

    ((float4*)hs)[tid] = ((const float4*)(hc + (size_t)b * 2 * HDIM))[tid];
    __syncthreads();

    // h fragment in registers (per warp, full row, float4-interleaved by lane)
    float4 hv[8];
#pragma unroll
    for (int i = 0; i < 8; i++) hv[i] = ((const float4*)hs)[lane + 32 * i];

    float4 ctx[8];
#pragma unroll
    for (int i = 0; i < 8; i++) ctx[i] = make_float4(0.f, 0.f, 0.f, 0.f);
    float M = -INFINITY, S = 0.f;

    // warp's 4 rows within this split's 32-row chunk
    const float* svb = sv + ((size_t)b * SLEN + sp * (SLEN / ATT_SPLIT) + warp * 4) * HDIM;

#pragma unroll
    for (int r = 0; r < 4; r++) {
        const float4* src = (const float4*)(svb + (size_t)r * HDIM);
        float4 v[8];
        float acc = 0.f;
#pragma unroll
        for (int i = 0; i < 8; i++) {
            v[i] = src[lane + 32 * i];
            acc += v[i].x * hv[i].x + v[i].y * hv[i].y + v[i].z * hv[i].z + v[i].w * hv[i].w;
        }
#pragma unroll
        for (int off = 16; off; off >>= 1) acc += __shfl_xor_sync(0xffffffffu, acc, off);

        float mx = fmaxf(M, acc);
        float scale = expf(M - mx);   // M = -inf -> 0
        float e = expf(acc - mx);
        S = S * scale + e;
#pragma unroll
        for (int i = 0; i < 8; i++) {
            ctx[i].x = ctx[i].x * scale + e * v[i].x;
            ctx[i].y = ctx[i].y * scale + e * v[i].y;
            ctx[i].z = ctx[i].z * scale + e * v[i].z;
            ctx[i].w = ctx[i].w * scale + e * v[i].w;
        }
        M = mx;
    }

    // per-warp results to smem
#pragma unroll
    for (int i = 0; i < 8; i++) ((float4*)wctx[warp])[lane + 32 * i] = ctx[i];
    if (lane == 0) { wms[warp][0] = M; wms[warp][1] = S; }
    __syncthreads();

    // combine 8 warps (all 256 threads, each owns one float4 dim-group)
    float Mg = -INFINITY;
#pragma unroll
    for (int w = 0; w < 8; w++) Mg = fmaxf(Mg, wms[w][0]);
    float Sg = 0.f;
    float4 c = make_float4(0.f, 0.f, 0.f, 0.f);
#pragma unroll
    for (int w = 0; w < 8; w++) {
        float wgt = expf(wms[w][0] - Mg);
        Sg += wgt * wms[w][1];
        float4 p = ((const float4*)wctx[w])[tid];
        c.x += wgt * p.x; c.y += wgt * p.y; c.z += wgt * p.z; c.w += wgt * p.w;
    }
    ((float4*)(pctx + ((size_t)(b * ATT_SPLIT + sp)) * HDIM))[tid] = c;
    if (tid == 0) {
        pms[(b * ATT_SPLIT + sp) * 2]     = Mg;
        pms[(b * ATT_SPLIT + sp) * 2 + 1] = Sg;
    }
}

// ---------------- attention combine: ctx -> hc[:, H:2H] ----------------
__global__ void attn_combine(const float* __restrict__ pctx, const float* __restrict__ pms,
                             float* __restrict__ hc) {
    const int b = blockIdx.x, tid = threadIdx.x;
    float Mi[ATT_SPLIT], Si[ATT_SPLIT];
    float Mg = -INFINITY;
#pragma unroll
    for (int i = 0; i < ATT_SPLIT; i++) {
        Mi[i] = pms[(b * ATT_SPLIT + i) * 2];
        Si[i] = pms[(b * ATT_SPLIT + i) * 2 + 1];
        Mg = fmaxf(Mg, Mi[i]);
    }
    float wsum = 0.f, wi[ATT_SPLIT];
#pragma unroll
    for (int i = 0; i < ATT_SPLIT; i++) {
        wi[i] = expf(Mi[i] - Mg);
        wsum += wi[i] * Si[i];
    }
    float inv = 1.f / wsum;
    float4 c = make_float4(0.f, 0.f, 0.f, 0.f);
#pragma unroll
    for (int i = 0; i < ATT_SPLIT; i++) {
        float4 p = ((const float4*)(pctx + ((size_t)(b * ATT_SPLIT + i)) * HDIM))[tid];
        c.x += wi[i] * p.x; c.y += wi[i] * p.y;
        c.z += wi[i] * p.z; c.w += wi[i] * p.w;
    }
    c.x *= inv; c.y *= inv; c.z *= inv; c.w *= inv;
    ((float4*)(hc + (size_t)b * 2 * HDIM + HDIM))[tid] = c;
}

// ---------------- logits reduce (vectorized): out = sum_s PO[s] + bias ----------------
__global__ void reduce_logits(const float* __restrict__ PO, const float* __restrict__ bout,
                              float* __restrict__ out) {
    int i4 = blockIdx.x * 256 + threadIdx.x;  // float4 id; B*V/4 = 512000
    int idx = i4 * 4;
    int n = idx % VOCAB;
    float4 v = *(const float4*)(bout + n);
#pragma unroll
    for (int s = 0; s < SPLIT_O; s++) {
        float4 p = *(const float4*)(PO + (size_t)s * (BATCH * VOCAB) + idx);
        v.x += p.x; v.y += p.y; v.z += p.z; v.w += p.w;
    }
    *(float4*)(out + idx) = v;
}

// ---------------- launch ----------------
extern "C" void kernel_launch(void* const* d_in, const int* in_sizes, int n_in,
                              void* d_out, int out_size) {
    const float* x    = (const float*)d_in[0];
    const float* h0   = (const float*)d_in[1];
    const float* c0   = (const float*)d_in[2];
    const float* sv   = (const float*)d_in[3];
    const float* Wmx  = (const float*)d_in[4];
    const float* bmx  = (const float*)d_in[5];
    const float* Wmh  = (const float*)d_in[6];
    const float* bmh  = (const float*)d_in[7];
    const float* Wx   = (const float*)d_in[8];
    const float* bx   = (const float*)d_in[9];
    const float* Wm   = (const float*)d_in[10];
    const float* bm   = (const float*)d_in[11];
    const float* Wout = (const float*)d_in[12];
    const float* bout = (const float*)d_in[13];
    float* out = (float*)d_out;

    float *m, *hc, *P1, *P2, *P3, *P4, *PO, *pctx, *pms;
    cudaGetSymbolAddress((void**)&m,    d_m);
    cudaGetSymbolAddress((void**)&hc,   d_hc);
    cudaGetSymbolAddress((void**)&P1,   d_P1);
    cudaGetSymbolAddress((void**)&P2,   d_P2);
    cudaGetSymbolAddress((void**)&P3,   d_P3);
    cudaGetSymbolAddress((void**)&P4,   d_P4);
    cudaGetSymbolAddress((void**)&PO,   d_PO);
    cudaGetSymbolAddress((void**)&pctx, d_pctx);
    cudaGetSymbolAddress((void**)&pms,  d_pms);

    cudaFuncSetAttribute(bf16gemm, cudaFuncAttributeMaxDynamicSharedMemorySize, GEMM_SMEM_BYTES);

    // fused launch 1: t1 = x@Wmx (8 blocks) | g1 = x@Wx (32 blocks) | t2 = h0@Wmh (8 blocks)
    {
        GemmSec s0 = { x,  Wmx, P1, EDIM, HDIM };
        GemmSec s1 = { x,  Wx,  P3, EDIM, 4 * HDIM };
        GemmSec s2 = { h0, Wmh, P2, HDIM, HDIM };
        bf16gemm<<<dim3(8 + 32 + 8, SPLIT_1), 256, GEMM_SMEM_BYTES>>>(s0, s1, s2, 8, 32);
    }

    m_kernel<<<(BATCH * HDIM) / 256, 256>>>(P1, P2, bmx, bmh, m);

    // g2 = m@Wm, K=1024
    {
        GemmSec sg = { m, Wm, P4, HDIM, 4 * HDIM };
        bf16gemm<<<dim3(4 * HDIM / 128, SPLIT_G2), 256, GEMM_SMEM_BYTES>>>(sg, sg, sg, 32, 0);
    }

    gates_kernel<<<(BATCH * HDIM) / 256, 256>>>(P3, P4, bx, bm, c0, hc);

    // fused attention (single pass over sv, register-resident)
    attn_partial<<<dim3(BATCH, ATT_SPLIT), 256>>>(hc, sv, pctx, pms);
    attn_combine<<<BATCH, 256>>>(pctx, pms, hc);

    // logits = [h|context] @ Wout, K=2048, split-K 2 + reduce(+bias)
    {
        GemmSec so = { hc, Wout, PO, 2 * HDIM, VOCAB };
        bf16gemm<<<dim3(VOCAB / 128, SPLIT_O), 256, GEMM_SMEM_BYTES>>>(so, so, so, VOCAB / 128, 0);
    }

    reduce_logits<<<(BATCH * VOCAB) / (256 * 4), 256>>>(PO, bout, out);
}

// round 15
// speedup vs baseline: 1.0361x; 1.0361x over previous
#include <cuda_runtime.h>
#include <cstdint>
#include <cstddef>
#include <math.h>

// Problem dims
#define BATCH 64
#define EDIM 2048
#define HDIM 1024
#define SLEN 512
#define VOCAB 32000

#define SPLIT_1  4    // split-K for fused first launch (t1|g1|t2)
#define SPLIT_G2 4    // split-K for g2 (m@Wm)
#define ATT_SPLIT 16  // split-S for attention

// ---------------- scratch (device globals; no allocation allowed) ----------------
__device__ float d_m   [BATCH * HDIM];
__device__ float d_hc  [BATCH * 2 * HDIM];
__device__ float d_P1  [SPLIT_1  * BATCH * HDIM];       // partials x@Wmx
__device__ float d_P2  [SPLIT_1  * BATCH * HDIM];       // partials h0@Wmh
__device__ float d_P3  [SPLIT_1  * BATCH * 4 * HDIM];   // partials x@Wx
__device__ float d_P4  [SPLIT_G2 * BATCH * 4 * HDIM];   // partials m@Wm
__device__ float d_pctx[BATCH * ATT_SPLIT * HDIM];
__device__ float d_pms [BATCH * ATT_SPLIT * 2];

// ---------------- helpers ----------------
// pack two fp32 into bf16x2 hi parts + bf16x2 lo residuals (memory order: lo half = x)
__device__ __forceinline__ void split2(float x, float y, unsigned& hi, unsigned& lo) {
    asm("cvt.rn.bf16x2.f32 %0, %1, %2;" : "=r"(hi) : "f"(y), "f"(x));
    float hx = __uint_as_float(hi << 16);
    float hy = __uint_as_float(hi & 0xffff0000u);
    asm("cvt.rn.bf16x2.f32 %0, %1, %2;" : "=r"(lo) : "f"(y - hy), "f"(x - hx));
}

__device__ __forceinline__ void ldm_x4(unsigned* r, unsigned saddr) {
    asm volatile("ldmatrix.sync.aligned.m8n8.x4.shared.b16 {%0,%1,%2,%3}, [%4];"
                 : "=r"(r[0]), "=r"(r[1]), "=r"(r[2]), "=r"(r[3]) : "r"(saddr));
}
__device__ __forceinline__ void ldm_x4t(unsigned* r, unsigned saddr) {
    asm volatile("ldmatrix.sync.aligned.m8n8.x4.trans.shared.b16 {%0,%1,%2,%3}, [%4];"
                 : "=r"(r[0]), "=r"(r[1]), "=r"(r[2]), "=r"(r[3]) : "r"(saddr));
}

#define MMA_BF16(d, a, b0, b1) \
    asm volatile("mma.sync.aligned.m16n8k16.row.col.f32.bf16.bf16.f32 " \
        "{%0,%1,%2,%3}, {%4,%5,%6,%7}, {%8,%9}, {%0,%1,%2,%3};" \
        : "+f"(d[0]), "+f"(d[1]), "+f"(d[2]), "+f"(d[3]) \
        : "r"(a[0]), "r"(a[1]), "r"(a[2]), "r"(a[3]), "r"(b0), "r"(b1))

// Smem strides in halfs (A rows 80B -> 5r mod 8 distinct; B rows 272B -> 17k mod 8 distinct)
#define A_ST 40
#define B_ST 136
#define A_BUF (64 * A_ST)   // 2560 halfs per buffer
#define B_BUF (32 * B_ST)   // 4352 halfs per buffer
#define GEMM_SMEM_BYTES ((2 * A_BUF * 2 + 2 * B_BUF * 2) * 2)  // 55296 B

// GEMM section: C[64][N] (+split-K partials) = A[64][K] @ W[K][N] (+bias if Sy==1 && bias)
struct GemmSec {
    const float* A;
    const float* W;
    float*       C;
    const float* bias;   // applied only when gridDim.y == 1
    int          K;
    int          N;
};

// ---------------- bf16 3-term GEMM (proven core, 3-section dispatch) ----------------
__global__ __launch_bounds__(256) void bf16gemm(
    GemmSec s0, GemmSec s1, GemmSec s2, int nb0, int nb1)
{
    extern __shared__ unsigned short sh[];
    unsigned short* Ahi = sh;                    // [2][A_BUF]
    unsigned short* Alo = sh + 2 * A_BUF;        // [2][A_BUF]
    unsigned short* Bhi = sh + 4 * A_BUF;        // [2][B_BUF]
    unsigned short* Blo = Bhi + 2 * B_BUF;       // [2][B_BUF]

    const int tid  = threadIdx.x;
    const int lane = tid & 31;
    const int warp = tid >> 5;
    const int wm   = warp & 1;
    const int wn   = warp >> 1;
    const int qr   = lane >> 2;
    const int qc   = lane & 3;

    // 3-section dispatch
    GemmSec s;
    int nbx = blockIdx.x;
    if (nbx < nb0)             { s = s0; }
    else if (nbx < nb0 + nb1)  { s = s1; nbx -= nb0; }
    else                       { s = s2; nbx -= nb0 + nb1; }
    const float* A = s.A;
    const float* W = s.W;
    const int K = s.K;
    const int N = s.N;
    const int n0 = nbx * 128;

    const int Sy   = gridDim.y;
    const int Kc   = K / Sy;
    const int kbeg = blockIdx.y * Kc;
    const int nk   = Kc / 32;
    float* Cb = (Sy > 1) ? (s.C + (size_t)blockIdx.y * 64 * N) : s.C;
    const float* bias = (Sy > 1) ? nullptr : s.bias;

    const int aR = tid >> 2;
    const int aC = (tid & 3) * 8;
    const int bR = tid >> 3;
    const int bC = (tid & 7) * 16;

    float4 ar0, ar1, br0, br1, br2, br3;
    {
        const float* ag = A + (size_t)aR * K + kbeg + aC;
        ar0 = *(const float4*)ag;
        ar1 = *(const float4*)(ag + 4);
        const float* bg = W + (size_t)(kbeg + bR) * N + n0 + bC;
        br0 = *(const float4*)bg;
        br1 = *(const float4*)(bg + 4);
        br2 = *(const float4*)(bg + 8);
        br3 = *(const float4*)(bg + 12);
    }

    float d[2][4][4];
#pragma unroll
    for (int i = 0; i < 2; i++)
#pragma unroll
        for (int j = 0; j < 4; j++)
#pragma unroll
            for (int q = 0; q < 4; q++) d[i][j][q] = 0.f;

    const unsigned sAh = (unsigned)__cvta_generic_to_shared(Ahi);
    const unsigned sAl = (unsigned)__cvta_generic_to_shared(Alo);
    const unsigned sBh = (unsigned)__cvta_generic_to_shared(Bhi);
    const unsigned sBl = (unsigned)__cvta_generic_to_shared(Blo);

    for (int t = 0; t < nk; t++) {
        const int buf = t & 1;
        // ---- convert tile t -> buffer buf ----
        {
            unsigned short* AhiB = Ahi + buf * A_BUF;
            unsigned short* AloB = Alo + buf * A_BUF;
            unsigned short* BhiB = Bhi + buf * B_BUF;
            unsigned short* BloB = Blo + buf * B_BUF;

            uint4 h, l;
            split2(ar0.x, ar0.y, h.x, l.x);
            split2(ar0.z, ar0.w, h.y, l.y);
            split2(ar1.x, ar1.y, h.z, l.z);
            split2(ar1.z, ar1.w, h.w, l.w);
            *(uint4*)&AhiB[aR * A_ST + aC] = h;
            *(uint4*)&AloB[aR * A_ST + aC] = l;

            split2(br0.x, br0.y, h.x, l.x);
            split2(br0.z, br0.w, h.y, l.y);
            split2(br1.x, br1.y, h.z, l.z);
            split2(br1.z, br1.w, h.w, l.w);
            *(uint4*)&BhiB[bR * B_ST + bC] = h;
            *(uint4*)&BloB[bR * B_ST + bC] = l;

            split2(br2.x, br2.y, h.x, l.x);
            split2(br2.z, br2.w, h.y, l.y);
            split2(br3.x, br3.y, h.z, l.z);
            split2(br3.z, br3.w, h.w, l.w);
            *(uint4*)&BhiB[bR * B_ST + bC + 8] = h;
            *(uint4*)&BloB[bR * B_ST + bC + 8] = l;
        }
        // ---- prefetch tile t+1 into registers ----
        if (t + 1 < nk) {
            const int k0 = kbeg + (t + 1) * 32;
            const float* ag = A + (size_t)aR * K + k0 + aC;
            ar0 = *(const float4*)ag;
            ar1 = *(const float4*)(ag + 4);
            const float* bg = W + (size_t)(k0 + bR) * N + n0 + bC;
            br0 = *(const float4*)bg;
            br1 = *(const float4*)(bg + 4);
            br2 = *(const float4*)(bg + 8);
            br3 = *(const float4*)(bg + 12);
        }
        __syncthreads();  // convert(t) visible; implies MMA(t-1) fully drained

        // ---- MMA from buffer buf: 2 k-chunks of 16 ----
#pragma unroll
        for (int kc = 0; kc < 2; kc++) {
            const unsigned aoff = (unsigned)((buf * A_BUF +
                (wm * 32 + (lane & 15)) * A_ST + kc * 16 + (lane >> 4) * 8) * 2);
            unsigned ah[2][4], al[2][4];
            ldm_x4(ah[0], sAh + aoff);
            ldm_x4(ah[1], sAh + aoff + 16 * A_ST * 2);
            ldm_x4(al[0], sAl + aoff);
            ldm_x4(al[1], sAl + aoff + 16 * A_ST * 2);

            const unsigned boff = (unsigned)((buf * B_BUF +
                (kc * 16 + (lane & 15)) * B_ST + wn * 32 + (lane >> 4) * 8) * 2);
            unsigned bh[2][4], bl[2][4];
            ldm_x4t(bh[0], sBh + boff);
            ldm_x4t(bh[1], sBh + boff + 16 * 2);
            ldm_x4t(bl[0], sBl + boff);
            ldm_x4t(bl[1], sBl + boff + 16 * 2);

#pragma unroll
            for (int mi = 0; mi < 2; mi++)
#pragma unroll
                for (int ni = 0; ni < 4; ni++) {
                    const int p = ni >> 1, q = (ni & 1) * 2;
                    MMA_BF16(d[mi][ni], ah[mi], bh[p][q], bh[p][q + 1]);
                    MMA_BF16(d[mi][ni], al[mi], bh[p][q], bh[p][q + 1]);
                    MMA_BF16(d[mi][ni], ah[mi], bl[p][q], bl[p][q + 1]);
                }
        }
    }

#pragma unroll
    for (int mi = 0; mi < 2; mi++) {
        const int r = wm * 32 + mi * 16 + qr;
#pragma unroll
        for (int ni = 0; ni < 4; ni++) {
            const int c = n0 + wn * 32 + ni * 8 + qc * 2;
            float2 v0 = make_float2(d[mi][ni][0], d[mi][ni][1]);
            float2 v1 = make_float2(d[mi][ni][2], d[mi][ni][3]);
            if (bias) {
                float2 bb = *(const float2*)(bias + c);
                v0.x += bb.x; v0.y += bb.y; v1.x += bb.x; v1.y += bb.y;
            }
            *(float2*)(Cb + (size_t)r * N + c)       = v0;
            *(float2*)(Cb + (size_t)(r + 8) * N + c) = v1;
        }
    }
}

// ---------------- m = (x@Wmx + bmx) * (h0@Wmh + bmh) ----------------
__global__ void m_kernel(const float* __restrict__ P1, const float* __restrict__ P2,
                         const float* __restrict__ bmx, const float* __restrict__ bmh,
                         float* __restrict__ m) {
    int idx = blockIdx.x * 256 + threadIdx.x;
    int j = idx & (HDIM - 1);
    float a = bmx[j], c = bmh[j];
#pragma unroll
    for (int s = 0; s < SPLIT_1; s++) {
        a += P1[(size_t)s * (BATCH * HDIM) + idx];
        c += P2[(size_t)s * (BATCH * HDIM) + idx];
    }
    m[idx] = a * c;
}

// ---------------- gates: reduce partials, LSTM cell -> h into hc[:, :H] ----------------
__global__ void gates_kernel(const float* __restrict__ P3, const float* __restrict__ P4,
                             const float* __restrict__ bx, const float* __restrict__ bm,
                             const float* __restrict__ c0, float* __restrict__ hc) {
    int idx = blockIdx.x * 256 + threadIdx.x;
    int b = idx >> 10, j = idx & (HDIM - 1);
    float gv[4];
#pragma unroll
    for (int q = 0; q < 4; q++) {
        int colq = j + q * HDIM;
        float g = bx[colq] + bm[colq];
        size_t off = (size_t)b * (4 * HDIM) + colq;
#pragma unroll
        for (int s = 0; s < SPLIT_1; s++)
            g += P3[(size_t)s * (BATCH * 4 * HDIM) + off];
#pragma unroll
        for (int s = 0; s < SPLIT_G2; s++)
            g += P4[(size_t)s * (BATCH * 4 * HDIM) + off];
        gv[q] = g;
    }
    float f  = 1.f / (1.f + expf(-gv[0]));
    float ii = 1.f / (1.f + expf(-gv[1]));
    float o  = 1.f / (1.f + expf(-gv[2]));
    float ct = tanhf(gv[3]);
    float c  = f * c0[idx] + ii * ct;
    hc[(size_t)b * (2 * HDIM) + j] = o * tanhf(c);
}

// ---------------- fused attention partial (flash-style online softmax, r13 proven) ----------------
__global__ __launch_bounds__(256) void attn_partial(
    const float* __restrict__ hc, const float* __restrict__ sv,
    float* __restrict__ pctx, float* __restrict__ pms)
{
    __shared__ float hs[HDIM];
    __shared__ float rows[8][HDIM];
    __shared__ float sscore[8];

    const int b   = blockIdx.x;
    const int sp  = blockIdx.y;
    const int tid = threadIdx.x;
    const int warp = tid >> 5, lane = tid & 31;

    ((float4*)hs)[tid] = ((const float4*)(hc + (size_t)b * 2 * HDIM))[tid];

    float4 ctx = make_float4(0.f, 0.f, 0.f, 0.f);
    float M = -INFINITY, S = 0.f;

    const float* svb = sv + ((size_t)b * SLEN + sp * (SLEN / ATT_SPLIT)) * HDIM;
    const int niter = (SLEN / ATT_SPLIT) / 8;

    for (int it = 0; it < niter; it++) {
        __syncthreads();
        const float4* src = (const float4*)(svb + (size_t)(it * 8 + warp) * HDIM);
        float acc = 0.f;
#pragma unroll
        for (int i = 0; i < 8; i++) {
            float4 v = src[lane + 32 * i];
            ((float4*)rows[warp])[lane + 32 * i] = v;
            float4 hv = ((const float4*)hs)[lane + 32 * i];
            acc += v.x * hv.x + v.y * hv.y + v.z * hv.z + v.w * hv.w;
        }
#pragma unroll
        for (int off = 16; off; off >>= 1) acc += __shfl_xor_sync(0xffffffffu, acc, off);
        if (lane == 0) sscore[warp] = acc;
        __syncthreads();

        float sc[8];
        float mx = M;
#pragma unroll
        for (int w = 0; w < 8; w++) { sc[w] = sscore[w]; mx = fmaxf(mx, sc[w]); }
        float scale = expf(M - mx);
        float e[8], esum = 0.f;
#pragma unroll
        for (int w = 0; w < 8; w++) { e[w] = expf(sc[w] - mx); esum += e[w]; }
        S = S * scale + esum;
        ctx.x *= scale; ctx.y *= scale; ctx.z *= scale; ctx.w *= scale;
#pragma unroll
        for (int w = 0; w < 8; w++) {
            float4 r = ((const float4*)rows[w])[tid];
            ctx.x += e[w] * r.x; ctx.y += e[w] * r.y;
            ctx.z += e[w] * r.z; ctx.w += e[w] * r.w;
        }
        M = mx;
    }

    ((float4*)(pctx + ((size_t)(b * ATT_SPLIT + sp)) * HDIM))[tid] = ctx;
    if (tid == 0) {
        pms[(b * ATT_SPLIT + sp) * 2]     = M;
        pms[(b * ATT_SPLIT + sp) * 2 + 1] = S;
    }
}

// ---------------- attention combine: ctx -> hc[:, H:2H] ----------------
__global__ void attn_combine(const float* __restrict__ pctx, const float* __restrict__ pms,
                             float* __restrict__ hc) {
    const int b = blockIdx.x, tid = threadIdx.x;
    float Mi[ATT_SPLIT], Si[ATT_SPLIT];
    float Mg = -INFINITY;
#pragma unroll
    for (int i = 0; i < ATT_SPLIT; i++) {
        Mi[i] = pms[(b * ATT_SPLIT + i) * 2];
        Si[i] = pms[(b * ATT_SPLIT + i) * 2 + 1];
        Mg = fmaxf(Mg, Mi[i]);
    }
    float wsum = 0.f, wi[ATT_SPLIT];
#pragma unroll
    for (int i = 0; i < ATT_SPLIT; i++) {
        wi[i] = expf(Mi[i] - Mg);
        wsum += wi[i] * Si[i];
    }
    float inv = 1.f / wsum;
    float4 c = make_float4(0.f, 0.f, 0.f, 0.f);
#pragma unroll
    for (int i = 0; i < ATT_SPLIT; i++) {
        float4 p = ((const float4*)(pctx + ((size_t)(b * ATT_SPLIT + i)) * HDIM))[tid];
        c.x += wi[i] * p.x; c.y += wi[i] * p.y;
        c.z += wi[i] * p.z; c.w += wi[i] * p.w;
    }
    c.x *= inv; c.y *= inv; c.z *= inv; c.w *= inv;
    ((float4*)(hc + (size_t)b * 2 * HDIM + HDIM))[tid] = c;
}

// ---------------- launch ----------------
extern "C" void kernel_launch(void* const* d_in, const int* in_sizes, int n_in,
                              void* d_out, int out_size) {
    const float* x    = (const float*)d_in[0];
    const float* h0   = (const float*)d_in[1];
    const float* c0   = (const float*)d_in[2];
    const float* sv   = (const float*)d_in[3];
    const float* Wmx  = (const float*)d_in[4];
    const float* bmx  = (const float*)d_in[5];
    const float* Wmh  = (const float*)d_in[6];
    const float* bmh  = (const float*)d_in[7];
    const float* Wx   = (const float*)d_in[8];
    const float* bx   = (const float*)d_in[9];
    const float* Wm   = (const float*)d_in[10];
    const float* bm   = (const float*)d_in[11];
    const float* Wout = (const float*)d_in[12];
    const float* bout = (const float*)d_in[13];
    float* out = (float*)d_out;

    float *m, *hc, *P1, *P2, *P3, *P4, *pctx, *pms;
    cudaGetSymbolAddress((void**)&m,    d_m);
    cudaGetSymbolAddress((void**)&hc,   d_hc);
    cudaGetSymbolAddress((void**)&P1,   d_P1);
    cudaGetSymbolAddress((void**)&P2,   d_P2);
    cudaGetSymbolAddress((void**)&P3,   d_P3);
    cudaGetSymbolAddress((void**)&P4,   d_P4);
    cudaGetSymbolAddress((void**)&pctx, d_pctx);
    cudaGetSymbolAddress((void**)&pms,  d_pms);

    cudaFuncSetAttribute(bf16gemm, cudaFuncAttributeMaxDynamicSharedMemorySize, GEMM_SMEM_BYTES);

    // fused launch 1: t1 = x@Wmx (8 blocks) | g1 = x@Wx (32 blocks) | t2 = h0@Wmh (8 blocks)
    {
        GemmSec s0 = { x,  Wmx, P1, nullptr, EDIM, HDIM };
        GemmSec s1 = { x,  Wx,  P3, nullptr, EDIM, 4 * HDIM };
        GemmSec s2 = { h0, Wmh, P2, nullptr, HDIM, HDIM };
        bf16gemm<<<dim3(8 + 32 + 8, SPLIT_1), 256, GEMM_SMEM_BYTES>>>(s0, s1, s2, 8, 32);
    }

    m_kernel<<<(BATCH * HDIM) / 256, 256>>>(P1, P2, bmx, bmh, m);

    // g2 = m@Wm, K=1024
    {
        GemmSec sg = { m, Wm, P4, nullptr, HDIM, 4 * HDIM };
        bf16gemm<<<dim3(4 * HDIM / 128, SPLIT_G2), 256, GEMM_SMEM_BYTES>>>(sg, sg, sg, 32, 0);
    }

    gates_kernel<<<(BATCH * HDIM) / 256, 256>>>(P3, P4, bx, bm, c0, hc);

    // fused attention (single pass over sv)
    attn_partial<<<dim3(BATCH, ATT_SPLIT), 256>>>(hc, sv, pctx, pms);
    attn_combine<<<BATCH, 256>>>(pctx, pms, hc);

    // logits = [h|context] @ Wout + bout, split-K 1 (bias fused, direct to out, single wave)
    {
        GemmSec so = { hc, Wout, out, bout, 2 * HDIM, VOCAB };
        bf16gemm<<<dim3(VOCAB / 128, 1), 256, GEMM_SMEM_BYTES>>>(so, so, so, VOCAB / 128, 0);
    }
}

// round 16
// speedup vs baseline: 1.0843x; 1.0465x over previous
#include <cuda_runtime.h>
#include <cstdint>
#include <cstddef>
#include <math.h>

// Problem dims
#define BATCH 64
#define EDIM 2048
#define HDIM 1024
#define SLEN 512
#define VOCAB 32000

#define SPLIT_1  4    // split-K for fused first launch (t1|g1|t2)
#define SPLIT_G2 4    // split-K for g2 (m@Wm)
#define ATT_SPLIT 16  // split-S for attention

// ---------------- scratch (device globals; no allocation allowed) ----------------
__device__ float d_m   [BATCH * HDIM];
__device__ float d_hc  [BATCH * 2 * HDIM];
__device__ float d_P1  [SPLIT_1  * BATCH * HDIM];       // partials x@Wmx
__device__ float d_P2  [SPLIT_1  * BATCH * HDIM];       // partials h0@Wmh
__device__ float d_P3  [SPLIT_1  * BATCH * 4 * HDIM];   // partials x@Wx
__device__ float d_P4  [SPLIT_G2 * BATCH * 4 * HDIM];   // partials m@Wm
__device__ float d_PO  [BATCH * VOCAB];                 // logits partial (h-half)
__device__ float d_pctx[BATCH * ATT_SPLIT * HDIM];
__device__ float d_pms [BATCH * ATT_SPLIT * 2];

// ---------------- helpers ----------------
// pack two fp32 into bf16x2 hi parts + bf16x2 lo residuals (memory order: lo half = x)
__device__ __forceinline__ void split2(float x, float y, unsigned& hi, unsigned& lo) {
    asm("cvt.rn.bf16x2.f32 %0, %1, %2;" : "=r"(hi) : "f"(y), "f"(x));
    float hx = __uint_as_float(hi << 16);
    float hy = __uint_as_float(hi & 0xffff0000u);
    asm("cvt.rn.bf16x2.f32 %0, %1, %2;" : "=r"(lo) : "f"(y - hy), "f"(x - hx));
}

__device__ __forceinline__ void ldm_x4(unsigned* r, unsigned saddr) {
    asm volatile("ldmatrix.sync.aligned.m8n8.x4.shared.b16 {%0,%1,%2,%3}, [%4];"
                 : "=r"(r[0]), "=r"(r[1]), "=r"(r[2]), "=r"(r[3]) : "r"(saddr));
}
__device__ __forceinline__ void ldm_x4t(unsigned* r, unsigned saddr) {
    asm volatile("ldmatrix.sync.aligned.m8n8.x4.trans.shared.b16 {%0,%1,%2,%3}, [%4];"
                 : "=r"(r[0]), "=r"(r[1]), "=r"(r[2]), "=r"(r[3]) : "r"(saddr));
}

#define MMA_BF16(d, a, b0, b1) \
    asm volatile("mma.sync.aligned.m16n8k16.row.col.f32.bf16.bf16.f32 " \
        "{%0,%1,%2,%3}, {%4,%5,%6,%7}, {%8,%9}, {%0,%1,%2,%3};" \
        : "+f"(d[0]), "+f"(d[1]), "+f"(d[2]), "+f"(d[3]) \
        : "r"(a[0]), "r"(a[1]), "r"(a[2]), "r"(a[3]), "r"(b0), "r"(b1))

// Smem strides in halfs (A rows 80B -> 5r mod 8 distinct; B rows 272B -> 17k mod 8 distinct)
#define A_ST 40
#define B_ST 136
#define A_BUF (64 * A_ST)   // 2560 halfs per buffer
#define B_BUF (32 * B_ST)   // 4352 halfs per buffer
#define GEMM_SMEM_BYTES ((2 * A_BUF * 2 + 2 * B_BUF * 2) * 2)  // 55296 B

// GEMM section: C[64][N] (+split-K partials) = A[64][K] @ W[K][N]
// lda = row stride of A. When gridDim.y == 1: += bias[n] and += add[r*N+n] if set.
struct GemmSec {
    const float* A;
    const float* W;
    float*       C;
    const float* bias;
    const float* add;
    int          K;
    int          N;
    int          lda;
};

// ---------------- bf16 3-term GEMM (proven core, 3-section dispatch) ----------------
__global__ __launch_bounds__(256) void bf16gemm(
    GemmSec s0, GemmSec s1, GemmSec s2, int nb0, int nb1)
{
    extern __shared__ unsigned short sh[];
    unsigned short* Ahi = sh;                    // [2][A_BUF]
    unsigned short* Alo = sh + 2 * A_BUF;        // [2][A_BUF]
    unsigned short* Bhi = sh + 4 * A_BUF;        // [2][B_BUF]
    unsigned short* Blo = Bhi + 2 * B_BUF;       // [2][B_BUF]

    const int tid  = threadIdx.x;
    const int lane = tid & 31;
    const int warp = tid >> 5;
    const int wm   = warp & 1;
    const int wn   = warp >> 1;
    const int qr   = lane >> 2;
    const int qc   = lane & 3;

    // 3-section dispatch
    GemmSec s;
    int nbx = blockIdx.x;
    if (nbx < nb0)             { s = s0; }
    else if (nbx < nb0 + nb1)  { s = s1; nbx -= nb0; }
    else                       { s = s2; nbx -= nb0 + nb1; }
    const float* A = s.A;
    const float* W = s.W;
    const int K   = s.K;
    const int N   = s.N;
    const int lda = s.lda;
    const int n0  = nbx * 128;

    const int Sy   = gridDim.y;
    const int Kc   = K / Sy;
    const int kbeg = blockIdx.y * Kc;
    const int nk   = Kc / 32;
    float* Cb = (Sy > 1) ? (s.C + (size_t)blockIdx.y * 64 * N) : s.C;
    const float* bias = (Sy > 1) ? nullptr : s.bias;
    const float* add  = (Sy > 1) ? nullptr : s.add;

    const int aR = tid >> 2;
    const int aC = (tid & 3) * 8;
    const int bR = tid >> 3;
    const int bC = (tid & 7) * 16;

    float4 ar0, ar1, br0, br1, br2, br3;
    {
        const float* ag = A + (size_t)aR * lda + kbeg + aC;
        ar0 = *(const float4*)ag;
        ar1 = *(const float4*)(ag + 4);
        const float* bg = W + (size_t)(kbeg + bR) * N + n0 + bC;
        br0 = *(const float4*)bg;
        br1 = *(const float4*)(bg + 4);
        br2 = *(const float4*)(bg + 8);
        br3 = *(const float4*)(bg + 12);
    }

    float d[2][4][4];
#pragma unroll
    for (int i = 0; i < 2; i++)
#pragma unroll
        for (int j = 0; j < 4; j++)
#pragma unroll
            for (int q = 0; q < 4; q++) d[i][j][q] = 0.f;

    const unsigned sAh = (unsigned)__cvta_generic_to_shared(Ahi);
    const unsigned sAl = (unsigned)__cvta_generic_to_shared(Alo);
    const unsigned sBh = (unsigned)__cvta_generic_to_shared(Bhi);
    const unsigned sBl = (unsigned)__cvta_generic_to_shared(Blo);

    for (int t = 0; t < nk; t++) {
        const int buf = t & 1;
        // ---- convert tile t -> buffer buf ----
        {
            unsigned short* AhiB = Ahi + buf * A_BUF;
            unsigned short* AloB = Alo + buf * A_BUF;
            unsigned short* BhiB = Bhi + buf * B_BUF;
            unsigned short* BloB = Blo + buf * B_BUF;

            uint4 h, l;
            split2(ar0.x, ar0.y, h.x, l.x);
            split2(ar0.z, ar0.w, h.y, l.y);
            split2(ar1.x, ar1.y, h.z, l.z);
            split2(ar1.z, ar1.w, h.w, l.w);
            *(uint4*)&AhiB[aR * A_ST + aC] = h;
            *(uint4*)&AloB[aR * A_ST + aC] = l;

            split2(br0.x, br0.y, h.x, l.x);
            split2(br0.z, br0.w, h.y, l.y);
            split2(br1.x, br1.y, h.z, l.z);
            split2(br1.z, br1.w, h.w, l.w);
            *(uint4*)&BhiB[bR * B_ST + bC] = h;
            *(uint4*)&BloB[bR * B_ST + bC] = l;

            split2(br2.x, br2.y, h.x, l.x);
            split2(br2.z, br2.w, h.y, l.y);
            split2(br3.x, br3.y, h.z, l.z);
            split2(br3.z, br3.w, h.w, l.w);
            *(uint4*)&BhiB[bR * B_ST + bC + 8] = h;
            *(uint4*)&BloB[bR * B_ST + bC + 8] = l;
        }
        // ---- prefetch tile t+1 into registers ----
        if (t + 1 < nk) {
            const int k0 = kbeg + (t + 1) * 32;
            const float* ag = A + (size_t)aR * lda + k0 + aC;
            ar0 = *(const float4*)ag;
            ar1 = *(const float4*)(ag + 4);
            const float* bg = W + (size_t)(k0 + bR) * N + n0 + bC;
            br0 = *(const float4*)bg;
            br1 = *(const float4*)(bg + 4);
            br2 = *(const float4*)(bg + 8);
            br3 = *(const float4*)(bg + 12);
        }
        __syncthreads();  // convert(t) visible; implies MMA(t-1) fully drained

        // ---- MMA from buffer buf: 2 k-chunks of 16 ----
#pragma unroll
        for (int kc = 0; kc < 2; kc++) {
            const unsigned aoff = (unsigned)((buf * A_BUF +
                (wm * 32 + (lane & 15)) * A_ST + kc * 16 + (lane >> 4) * 8) * 2);
            unsigned ah[2][4], al[2][4];
            ldm_x4(ah[0], sAh + aoff);
            ldm_x4(ah[1], sAh + aoff + 16 * A_ST * 2);
            ldm_x4(al[0], sAl + aoff);
            ldm_x4(al[1], sAl + aoff + 16 * A_ST * 2);

            const unsigned boff = (unsigned)((buf * B_BUF +
                (kc * 16 + (lane & 15)) * B_ST + wn * 32 + (lane >> 4) * 8) * 2);
            unsigned bh[2][4], bl[2][4];
            ldm_x4t(bh[0], sBh + boff);
            ldm_x4t(bh[1], sBh + boff + 16 * 2);
            ldm_x4t(bl[0], sBl + boff);
            ldm_x4t(bl[1], sBl + boff + 16 * 2);

#pragma unroll
            for (int mi = 0; mi < 2; mi++)
#pragma unroll
                for (int ni = 0; ni < 4; ni++) {
                    const int p = ni >> 1, q = (ni & 1) * 2;
                    MMA_BF16(d[mi][ni], ah[mi], bh[p][q], bh[p][q + 1]);
                    MMA_BF16(d[mi][ni], al[mi], bh[p][q], bh[p][q + 1]);
                    MMA_BF16(d[mi][ni], ah[mi], bl[p][q], bl[p][q + 1]);
                }
        }
    }

#pragma unroll
    for (int mi = 0; mi < 2; mi++) {
        const int r = wm * 32 + mi * 16 + qr;
#pragma unroll
        for (int ni = 0; ni < 4; ni++) {
            const int c = n0 + wn * 32 + ni * 8 + qc * 2;
            float2 v0 = make_float2(d[mi][ni][0], d[mi][ni][1]);
            float2 v1 = make_float2(d[mi][ni][2], d[mi][ni][3]);
            if (bias) {
                float2 bb = *(const float2*)(bias + c);
                v0.x += bb.x; v0.y += bb.y; v1.x += bb.x; v1.y += bb.y;
            }
            if (add) {
                float2 a0 = *(const float2*)(add + (size_t)r * N + c);
                float2 a1 = *(const float2*)(add + (size_t)(r + 8) * N + c);
                v0.x += a0.x; v0.y += a0.y; v1.x += a1.x; v1.y += a1.y;
            }
            *(float2*)(Cb + (size_t)r * N + c)       = v0;
            *(float2*)(Cb + (size_t)(r + 8) * N + c) = v1;
        }
    }
}

// ---------------- m = (x@Wmx + bmx) * (h0@Wmh + bmh) ----------------
__global__ void m_kernel(const float* __restrict__ P1, const float* __restrict__ P2,
                         const float* __restrict__ bmx, const float* __restrict__ bmh,
                         float* __restrict__ m) {
    int idx = blockIdx.x * 256 + threadIdx.x;
    int j = idx & (HDIM - 1);
    float a = bmx[j], c = bmh[j];
#pragma unroll
    for (int s = 0; s < SPLIT_1; s++) {
        a += P1[(size_t)s * (BATCH * HDIM) + idx];
        c += P2[(size_t)s * (BATCH * HDIM) + idx];
    }
    m[idx] = a * c;
}

// ---------------- gates: reduce partials, LSTM cell -> h into hc[:, :H] ----------------
__global__ void gates_kernel(const float* __restrict__ P3, const float* __restrict__ P4,
                             const float* __restrict__ bx, const float* __restrict__ bm,
                             const float* __restrict__ c0, float* __restrict__ hc) {
    int idx = blockIdx.x * 256 + threadIdx.x;
    int b = idx >> 10, j = idx & (HDIM - 1);
    float gv[4];
#pragma unroll
    for (int q = 0; q < 4; q++) {
        int colq = j + q * HDIM;
        float g = bx[colq] + bm[colq];
        size_t off = (size_t)b * (4 * HDIM) + colq;
#pragma unroll
        for (int s = 0; s < SPLIT_1; s++)
            g += P3[(size_t)s * (BATCH * 4 * HDIM) + off];
#pragma unroll
        for (int s = 0; s < SPLIT_G2; s++)
            g += P4[(size_t)s * (BATCH * 4 * HDIM) + off];
        gv[q] = g;
    }
    float f  = 1.f / (1.f + expf(-gv[0]));
    float ii = 1.f / (1.f + expf(-gv[1]));
    float o  = 1.f / (1.f + expf(-gv[2]));
    float ct = tanhf(gv[3]);
    float c  = f * c0[idx] + ii * ct;
    hc[(size_t)b * (2 * HDIM) + j] = o * tanhf(c);
}

// ---------------- fused attention partial (flash-style online softmax) ----------------
__global__ __launch_bounds__(256) void attn_partial(
    const float* __restrict__ hc, const float* __restrict__ sv,
    float* __restrict__ pctx, float* __restrict__ pms)
{
    __shared__ float hs[HDIM];
    __shared__ float rows[8][HDIM];
    __shared__ float sscore[8];

    const int b   = blockIdx.x;
    const int sp  = blockIdx.y;
    const int tid = threadIdx.x;
    const int warp = tid >> 5, lane = tid & 31;

    ((float4*)hs)[tid] = ((const float4*)(hc + (size_t)b * 2 * HDIM))[tid];

    float4 ctx = make_float4(0.f, 0.f, 0.f, 0.f);
    float M = -INFINITY, S = 0.f;

    const float* svb = sv + ((size_t)b * SLEN + sp * (SLEN / ATT_SPLIT)) * HDIM;
    const int niter = (SLEN / ATT_SPLIT) / 8;

    for (int it = 0; it < niter; it++) {
        __syncthreads();
        const float4* src = (const float4*)(svb + (size_t)(it * 8 + warp) * HDIM);
        float acc = 0.f;
#pragma unroll
        for (int i = 0; i < 8; i++) {
            float4 v = src[lane + 32 * i];
            ((float4*)rows[warp])[lane + 32 * i] = v;
            float4 hv = ((const float4*)hs)[lane + 32 * i];
            acc += v.x * hv.x + v.y * hv.y + v.z * hv.z + v.w * hv.w;
        }
#pragma unroll
        for (int off = 16; off; off >>= 1) acc += __shfl_xor_sync(0xffffffffu, acc, off);
        if (lane == 0) sscore[warp] = acc;
        __syncthreads();

        float sc[8];
        float mx = M;
#pragma unroll
        for (int w = 0; w < 8; w++) { sc[w] = sscore[w]; mx = fmaxf(mx, sc[w]); }
        float scale = expf(M - mx);
        float e[8], esum = 0.f;
#pragma unroll
        for (int w = 0; w < 8; w++) { e[w] = expf(sc[w] - mx); esum += e[w]; }
        S = S * scale + esum;
        ctx.x *= scale; ctx.y *= scale; ctx.z *= scale; ctx.w *= scale;
#pragma unroll
        for (int w = 0; w < 8; w++) {
            float4 r = ((const float4*)rows[w])[tid];
            ctx.x += e[w] * r.x; ctx.y += e[w] * r.y;
            ctx.z += e[w] * r.z; ctx.w += e[w] * r.w;
        }
        M = mx;
    }

    ((float4*)(pctx + ((size_t)(b * ATT_SPLIT + sp)) * HDIM))[tid] = ctx;
    if (tid == 0) {
        pms[(b * ATT_SPLIT + sp) * 2]     = M;
        pms[(b * ATT_SPLIT + sp) * 2 + 1] = S;
    }
}

// ---------------- attention combine: ctx -> hc[:, H:2H] ----------------
__global__ void attn_combine(const float* __restrict__ pctx, const float* __restrict__ pms,
                             float* __restrict__ hc) {
    const int b = blockIdx.x, tid = threadIdx.x;
    float Mi[ATT_SPLIT], Si[ATT_SPLIT];
    float Mg = -INFINITY;
#pragma unroll
    for (int i = 0; i < ATT_SPLIT; i++) {
        Mi[i] = pms[(b * ATT_SPLIT + i) * 2];
        Si[i] = pms[(b * ATT_SPLIT + i) * 2 + 1];
        Mg = fmaxf(Mg, Mi[i]);
    }
    float wsum = 0.f, wi[ATT_SPLIT];
#pragma unroll
    for (int i = 0; i < ATT_SPLIT; i++) {
        wi[i] = expf(Mi[i] - Mg);
        wsum += wi[i] * Si[i];
    }
    float inv = 1.f / wsum;
    float4 c = make_float4(0.f, 0.f, 0.f, 0.f);
#pragma unroll
    for (int i = 0; i < ATT_SPLIT; i++) {
        float4 p = ((const float4*)(pctx + ((size_t)(b * ATT_SPLIT + i)) * HDIM))[tid];
        c.x += wi[i] * p.x; c.y += wi[i] * p.y;
        c.z += wi[i] * p.z; c.w += wi[i] * p.w;
    }
    c.x *= inv; c.y *= inv; c.z *= inv; c.w *= inv;
    ((float4*)(hc + (size_t)b * 2 * HDIM + HDIM))[tid] = c;
}

// ---------------- launch ----------------
extern "C" void kernel_launch(void* const* d_in, const int* in_sizes, int n_in,
                              void* d_out, int out_size) {
    const float* x    = (const float*)d_in[0];
    const float* h0   = (const float*)d_in[1];
    const float* c0   = (const float*)d_in[2];
    const float* sv   = (const float*)d_in[3];
    const float* Wmx  = (const float*)d_in[4];
    const float* bmx  = (const float*)d_in[5];
    const float* Wmh  = (const float*)d_in[6];
    const float* bmh  = (const float*)d_in[7];
    const float* Wx   = (const float*)d_in[8];
    const float* bx   = (const float*)d_in[9];
    const float* Wm   = (const float*)d_in[10];
    const float* bm   = (const float*)d_in[11];
    const float* Wout = (const float*)d_in[12];
    const float* bout = (const float*)d_in[13];
    float* out = (float*)d_out;

    float *m, *hc, *P1, *P2, *P3, *P4, *PO, *pctx, *pms;
    cudaGetSymbolAddress((void**)&m,    d_m);
    cudaGetSymbolAddress((void**)&hc,   d_hc);
    cudaGetSymbolAddress((void**)&P1,   d_P1);
    cudaGetSymbolAddress((void**)&P2,   d_P2);
    cudaGetSymbolAddress((void**)&P3,   d_P3);
    cudaGetSymbolAddress((void**)&P4,   d_P4);
    cudaGetSymbolAddress((void**)&PO,   d_PO);
    cudaGetSymbolAddress((void**)&pctx, d_pctx);
    cudaGetSymbolAddress((void**)&pms,  d_pms);

    // side stream + fork/join events for overlap (created once; host objects only)
    static cudaStream_t s2 = nullptr;
    static cudaEvent_t evFork = nullptr, evJoin = nullptr;
    if (!s2) {
        cudaStreamCreateWithFlags(&s2, cudaStreamNonBlocking);
        cudaEventCreateWithFlags(&evFork, cudaEventDisableTiming);
        cudaEventCreateWithFlags(&evJoin, cudaEventDisableTiming);
    }

    cudaFuncSetAttribute(bf16gemm, cudaFuncAttributeMaxDynamicSharedMemorySize, GEMM_SMEM_BYTES);

    // fused launch 1: t1 = x@Wmx (8 blocks) | g1 = x@Wx (32 blocks) | t2 = h0@Wmh (8 blocks)
    {
        GemmSec sA = { x,  Wmx, P1, nullptr, nullptr, EDIM, HDIM,     EDIM };
        GemmSec sB = { x,  Wx,  P3, nullptr, nullptr, EDIM, 4 * HDIM, EDIM };
        GemmSec sC = { h0, Wmh, P2, nullptr, nullptr, HDIM, HDIM,     HDIM };
        bf16gemm<<<dim3(8 + 32 + 8, SPLIT_1), 256, GEMM_SMEM_BYTES>>>(sA, sB, sC, 8, 32);
    }

    m_kernel<<<(BATCH * HDIM) / 256, 256>>>(P1, P2, bmx, bmh, m);

    // g2 = m@Wm, K=1024
    {
        GemmSec sg = { m, Wm, P4, nullptr, nullptr, HDIM, 4 * HDIM, HDIM };
        bf16gemm<<<dim3(4 * HDIM / 128, SPLIT_G2), 256, GEMM_SMEM_BYTES>>>(sg, sg, sg, 32, 0);
    }

    gates_kernel<<<(BATCH * HDIM) / 256, 256>>>(P3, P4, bx, bm, c0, hc);

    // fork: logits part 1 (h-half, K=0:1024) runs on s2 concurrently with attention
    cudaEventRecord(evFork, 0);
    cudaStreamWaitEvent(s2, evFork, 0);
    {
        GemmSec so = { hc, Wout, PO, nullptr, nullptr, HDIM, VOCAB, 2 * HDIM };
        bf16gemm<<<dim3(VOCAB / 128, 1), 256, GEMM_SMEM_BYTES, s2>>>(so, so, so, VOCAB / 128, 0);
    }

    // attention on default stream (single pass over sv)
    attn_partial<<<dim3(BATCH, ATT_SPLIT), 256>>>(hc, sv, pctx, pms);
    attn_combine<<<BATCH, 256>>>(pctx, pms, hc);

    // join: part 2 (ctx-half, K=1024:2048) adds PO + bias, writes out
    cudaEventRecord(evJoin, s2);
    cudaStreamWaitEvent(0, evJoin, 0);
    {
        GemmSec so = { hc + HDIM, Wout + (size_t)HDIM * VOCAB, out, bout, PO,
                       HDIM, VOCAB, 2 * HDIM };
        bf16gemm<<<dim3(VOCAB / 128, 1), 256, GEMM_SMEM_BYTES>>>(so, so, so, VOCAB / 128, 0);
    }
}